// round 12
// baseline (speedup 1.0000x reference)
#include <cuda_runtime.h>
#include <cuda_fp16.h>
#include <cstdint>
#include <math.h>

#define NN 50000
#define EE 800000
#define ET (NN + EE)          // 850000 edges incl. self loops

// ---------------- scratch (device globals; no allocation allowed) ----------
__device__ __half  g_xh[(size_t)NN * 128];   // x in fp16
__device__ __half  g_w1h[128 * 256];         // W1 fp16
__device__ __half  g_w2h[256 * 64];          // W2 fp16
__device__ __half2 g_h1h[(size_t)NN * 128];  // h1 fp16 (gather + att src)
__device__ __half2 g_hh [(size_t)NN * 128];  // elu(gat1) fp16 (input to GEMM2)
__device__ __half2 g_h2h[(size_t)NN * 32];   // h2 fp16
__device__ float   g_t [(size_t)NN * 64];    // decoder hidden
__device__ float g_as1[NN * 4];
__device__ float g_ad1[NN * 4];
__device__ float g_as2[NN];
__device__ float g_ad2[NN];
__device__ int   g_deg[NN];
__device__ int   g_off[NN + 1];
__device__ int   g_cur[NN];
__device__ int   g_srcid[ET];
__device__ int   g_ei64;

__device__ __forceinline__ float lrelu(float v) { return v >= 0.f ? v : 0.2f * v; }

__device__ __forceinline__ int load_edge(const int* __restrict__ ei, int j) {
    return g_ei64 ? ei[(size_t)j * 2] : ei[j];   // little-endian low word
}

__global__ void k_flag(float* __restrict__ z, float v) { z[0] = v; }

__global__ void k_zero_out(float* __restrict__ o, int n) {
    int i = blockIdx.x * blockDim.x + threadIdx.x;
    if (i < n) o[i] = 0.f;
}

// ------- init: zero degrees + att accumulators + dtype detect --------------
__global__ void k_init(const int* __restrict__ ei) {
    int i = blockIdx.x * blockDim.x + threadIdx.x;
    if (i < NN) {
        g_deg[i] = 0;
        g_as2[i] = 0.f; g_ad2[i] = 0.f;
        #pragma unroll
        for (int h = 0; h < 4; h++) { g_as1[i * 4 + h] = 0.f; g_ad1[i * 4 + h] = 0.f; }
    }
    if (i == 0) {
        int odd_nz = 0, even_nz = 0;
        for (int j = 0; j < 256; j += 2) {
            if (ei[j]     != 0) even_nz++;
            if (ei[j + 1] != 0) odd_nz++;
        }
        g_ei64 = (odd_nz == 0 && even_nz > 0) ? 1 : 0;
    }
}

// ------- fp32 -> fp16 conversion of x, W1, W2 (pairwise) --------------------
#define XPAIRS 3200000
#define W1PAIRS 16384
#define W2PAIRS 8192
__global__ void k_cvt(const float* __restrict__ x, const float* __restrict__ W1,
                      const float* __restrict__ W2) {
    int p = blockIdx.x * blockDim.x + threadIdx.x;
    if (p < XPAIRS) {
        float2 v = *(const float2*)&x[(size_t)p * 2];
        *(__half2*)&g_xh[(size_t)p * 2] = __floats2half2_rn(v.x, v.y);
    } else if (p < XPAIRS + W1PAIRS) {
        int q = p - XPAIRS;
        float2 v = *(const float2*)&W1[(size_t)q * 2];
        *(__half2*)&g_w1h[(size_t)q * 2] = __floats2half2_rn(v.x, v.y);
    } else if (p < XPAIRS + W1PAIRS + W2PAIRS) {
        int q = p - XPAIRS - W1PAIRS;
        float2 v = *(const float2*)&W2[(size_t)q * 2];
        *(__half2*)&g_w2h[(size_t)q * 2] = __floats2half2_rn(v.x, v.y);
    }
}

// ---------------- CSR build -------------------------------------------------
__global__ void k_count(const int* __restrict__ ei) {
    int e = blockIdx.x * blockDim.x + threadIdx.x;
    if (e >= ET) return;
    int dst = (e < EE) ? load_edge(ei, EE + e) : (e - EE);
    if ((unsigned)dst < (unsigned)NN) atomicAdd(&g_deg[dst], 1);
}

// single-block scan: 1024 threads x 49 elements
__global__ void k_scan1() {
    const int PER = 49;
    __shared__ int ws[32];
    int tid = threadIdx.x;
    int base = tid * PER;
    int sum = 0;
    for (int j = 0; j < PER; j++) { int idx = base + j; if (idx < NN) sum += g_deg[idx]; }
    int lane = tid & 31, w = tid >> 5;
    int v = sum;
    #pragma unroll
    for (int o = 1; o < 32; o <<= 1) {
        int t = __shfl_up_sync(0xffffffffu, v, o);
        if (lane >= o) v += t;
    }
    if (lane == 31) ws[w] = v;
    __syncthreads();
    if (w == 0) {
        int xv = ws[lane];
        #pragma unroll
        for (int o = 1; o < 32; o <<= 1) {
            int t = __shfl_up_sync(0xffffffffu, xv, o);
            if (lane >= o) xv += t;
        }
        ws[lane] = xv;
    }
    __syncthreads();
    int run = (v - sum) + (w > 0 ? ws[w - 1] : 0);
    for (int j = 0; j < PER; j++) {
        int idx = base + j;
        if (idx < NN) {
            int d = g_deg[idx];
            g_off[idx] = run; g_cur[idx] = run;
            run += d;
        }
    }
    if (tid == 0) g_off[NN] = ET;
}

__global__ void k_scatter(const int* __restrict__ ei) {
    int e = blockIdx.x * blockDim.x + threadIdx.x;
    if (e >= ET) return;
    int s, d;
    if (e < EE) { s = load_edge(ei, e); d = load_edge(ei, EE + e); }
    else        { s = d = e - EE; }
    if ((unsigned)d >= (unsigned)NN || (unsigned)s >= (unsigned)NN) return;
    int p = atomicAdd(&g_cur[d], 1);
    if ((unsigned)p < (unsigned)ET) g_srcid[p] = s;
}

// ------- fp16 tensor-core GEMM + fused attention-coefficient epilogue ------
template<int K, int HS>
__global__ void k_hgemm_att(const __half* __restrict__ A, const __half* __restrict__ B,
                            __half2* __restrict__ Ch, int M, int N,
                            const float* __restrict__ att_s, const float* __restrict__ att_d,
                            float* __restrict__ as_out, float* __restrict__ ad_out) {
    __shared__ __half As[128][40];
    __shared__ __half Bs[64][42];
    int bm = blockIdx.y * 128, bn = blockIdx.x * 64;
    int tid = threadIdx.x, lane = tid & 31, wid = tid >> 5;
    int wm = wid & 3, wn = wid >> 2;
    int g = lane >> 2, tc = lane & 3;
    float acc[2][4][4] = {};
    for (int k0 = 0; k0 < K; k0 += 32) {
        #pragma unroll
        for (int t = 0; t < 2; t++) {
            int i = tid + t * 256;
            int r = i >> 2, seg = i & 3;
            int row = bm + r;
            uint4 v = make_uint4(0u, 0u, 0u, 0u);
            if (row < M) v = *(const uint4*)&A[(size_t)row * K + k0 + seg * 8];
            *(uint4*)&As[r][seg * 8] = v;
        }
        #pragma unroll
        for (int t = 0; t < 4; t++) {
            int i = tid + t * 256;
            int kk = i >> 5, nn = (i & 31) * 2;
            __half2 v = *(const __half2*)&B[(size_t)(k0 + kk) * N + bn + nn];
            Bs[nn][kk]     = __low2half(v);
            Bs[nn + 1][kk] = __high2half(v);
        }
        __syncthreads();
        #pragma unroll
        for (int ks = 0; ks < 2; ks++) {
            int kb = ks * 16;
            uint32_t af[2][4], bf[4][2];
            #pragma unroll
            for (int mt = 0; mt < 2; mt++) {
                int r = wm * 32 + mt * 16 + g;
                af[mt][0] = *(const uint32_t*)&As[r][kb + tc * 2];
                af[mt][1] = *(const uint32_t*)&As[r + 8][kb + tc * 2];
                af[mt][2] = *(const uint32_t*)&As[r][kb + tc * 2 + 8];
                af[mt][3] = *(const uint32_t*)&As[r + 8][kb + tc * 2 + 8];
            }
            #pragma unroll
            for (int nt = 0; nt < 4; nt++) {
                int n = wn * 32 + nt * 8 + g;
                bf[nt][0] = *(const uint32_t*)&Bs[n][kb + tc * 2];
                bf[nt][1] = *(const uint32_t*)&Bs[n][kb + tc * 2 + 8];
            }
            #pragma unroll
            for (int mt = 0; mt < 2; mt++)
                #pragma unroll
                for (int nt = 0; nt < 4; nt++)
                    asm volatile(
                        "mma.sync.aligned.m16n8k16.row.col.f32.f16.f16.f32 "
                        "{%0,%1,%2,%3},{%4,%5,%6,%7},{%8,%9},{%0,%1,%2,%3};"
                        : "+f"(acc[mt][nt][0]), "+f"(acc[mt][nt][1]),
                          "+f"(acc[mt][nt][2]), "+f"(acc[mt][nt][3])
                        : "r"(af[mt][0]), "r"(af[mt][1]), "r"(af[mt][2]), "r"(af[mt][3]),
                          "r"(bf[nt][0]), "r"(bf[nt][1]));
        }
        __syncthreads();
    }
    int hh = bn >> 6;
    int N2 = N >> 1;
    #pragma unroll
    for (int mt = 0; mt < 2; mt++) {
        #pragma unroll
        for (int hf = 0; hf < 2; hf++) {
            int row = bm + wm * 32 + mt * 16 + g + hf * 8;
            float ps = 0.f, pd = 0.f;
            if (row < M) {
                #pragma unroll
                for (int nt = 0; nt < 4; nt++) {
                    int cl = wn * 32 + nt * 8 + tc * 2;
                    float v0 = acc[mt][nt][hf * 2 + 0];
                    float v1 = acc[mt][nt][hf * 2 + 1];
                    Ch[(size_t)row * N2 + ((bn + cl) >> 1)] = __floats2half2_rn(v0, v1);
                    ps += v0 * att_s[bn + cl] + v1 * att_s[bn + cl + 1];
                    pd += v0 * att_d[bn + cl] + v1 * att_d[bn + cl + 1];
                }
            }
            ps += __shfl_xor_sync(0xffffffffu, ps, 1);
            pd += __shfl_xor_sync(0xffffffffu, pd, 1);
            ps += __shfl_xor_sync(0xffffffffu, ps, 2);
            pd += __shfl_xor_sync(0xffffffffu, pd, 2);
            if (tc == 0 && row < M) {
                atomicAdd(&as_out[row * HS + hh], ps);
                atomicAdd(&ad_out[row * HS + hh], pd);
            }
        }
    }
}

// ------- GEMM fp32: BM=128, BN=64, BK=16; epi: 1 bias, 2 bias+elu (decoder) -
__global__ void k_gemm64(const float* __restrict__ A, const float* __restrict__ B,
                         float* __restrict__ C, int M, int K, int Nc,
                         const float* __restrict__ bias, int epi) {
    __shared__ float As[16][132];
    __shared__ float Bs[16][68];
    int bm = blockIdx.y * 128, bn = blockIdx.x * 64;
    int tid = threadIdx.x;
    int tx = tid & 15, ty = tid >> 4;
    float acc[8][4] = {};
    for (int k0 = 0; k0 < K; k0 += 16) {
        #pragma unroll
        for (int i = tid; i < 128 * 16; i += 256) {
            int r = i >> 4, c = i & 15;
            int gr = bm + r;
            As[c][r] = (gr < M) ? A[(size_t)gr * K + k0 + c] : 0.f;
        }
        #pragma unroll
        for (int i = tid; i < 16 * 64; i += 256) {
            int r = i >> 6, c = i & 63;
            Bs[r][c] = B[(size_t)(k0 + r) * Nc + bn + c];
        }
        __syncthreads();
        #pragma unroll
        for (int k = 0; k < 16; k++) {
            float a[8], b[4];
            #pragma unroll
            for (int u = 0; u < 8; u++) a[u] = As[k][ty * 8 + u];
            #pragma unroll
            for (int v = 0; v < 4; v++) b[v] = Bs[k][tx * 4 + v];
            #pragma unroll
            for (int u = 0; u < 8; u++)
                #pragma unroll
                for (int v = 0; v < 4; v++) acc[u][v] += a[u] * b[v];
        }
        __syncthreads();
    }
    float bb[4] = {0.f, 0.f, 0.f, 0.f};
    if (epi) {
        #pragma unroll
        for (int v = 0; v < 4; v++) bb[v] = bias[bn + tx * 4 + v];
    }
    #pragma unroll
    for (int u = 0; u < 8; u++) {
        int gr = bm + ty * 8 + u;
        if (gr < M) {
            float o[4];
            #pragma unroll
            for (int v = 0; v < 4; v++) {
                float t = acc[u][v] + bb[v];
                if (epi == 2) t = t > 0.f ? t : __expf(t) - 1.f;
                o[v] = t;
            }
            *(float4*)&C[(size_t)gr * Nc + bn + tx * 4] = make_float4(o[0], o[1], o[2], o[3]);
        }
    }
}

// ---- GAT layer-1 aggregation: 2 warps/node (feature split), unroll x4 -----
__global__ void k_agg1(const float* __restrict__ b1) {
    int gw = (blockIdx.x * blockDim.x + threadIdx.x) >> 5;
    int node = gw >> 1;
    int half = gw & 1;
    int lane = threadIdx.x & 31;
    if (node >= NN) return;
    int beg = g_off[node], end = g_off[node + 1];
    int hh = half * 2 + (lane >> 4);           // head of this lane's features
    float adh = g_ad1[node * 4 + hh];
    int fo = half * 64 + lane * 2;             // half2 offset within 128-half2 row

    float a0 = 0.f, a1 = 0.f, a2 = 0.f, a3 = 0.f, den = 0.f;
    int i = beg;
    for (; i + 4 <= end; i += 4) {
        int s0 = g_srcid[i], s1 = g_srcid[i + 1], s2 = g_srcid[i + 2], s3 = g_srcid[i + 3];
        float e0 = g_as1[s0 * 4 + hh], e1 = g_as1[s1 * 4 + hh];
        float e2 = g_as1[s2 * 4 + hh], e3 = g_as1[s3 * 4 + hh];
        uint2 v0 = *(const uint2*)&g_h1h[(size_t)s0 * 128 + fo];
        uint2 v1 = *(const uint2*)&g_h1h[(size_t)s1 * 128 + fo];
        uint2 v2 = *(const uint2*)&g_h1h[(size_t)s2 * 128 + fo];
        uint2 v3 = *(const uint2*)&g_h1h[(size_t)s3 * 128 + fo];
        float w0 = __expf(lrelu(e0 + adh));
        float w1 = __expf(lrelu(e1 + adh));
        float w2 = __expf(lrelu(e2 + adh));
        float w3 = __expf(lrelu(e3 + adh));
        den += (w0 + w1) + (w2 + w3);
        float2 f;
        f = __half22float2(*(__half2*)&v0.x); a0 += f.x * w0; a1 += f.y * w0;
        f = __half22float2(*(__half2*)&v0.y); a2 += f.x * w0; a3 += f.y * w0;
        f = __half22float2(*(__half2*)&v1.x); a0 += f.x * w1; a1 += f.y * w1;
        f = __half22float2(*(__half2*)&v1.y); a2 += f.x * w1; a3 += f.y * w1;
        f = __half22float2(*(__half2*)&v2.x); a0 += f.x * w2; a1 += f.y * w2;
        f = __half22float2(*(__half2*)&v2.y); a2 += f.x * w2; a3 += f.y * w2;
        f = __half22float2(*(__half2*)&v3.x); a0 += f.x * w3; a1 += f.y * w3;
        f = __half22float2(*(__half2*)&v3.y); a2 += f.x * w3; a3 += f.y * w3;
    }
    for (; i < end; i++) {
        int s = g_srcid[i];
        float w = __expf(lrelu(g_as1[s * 4 + hh] + adh));
        den += w;
        uint2 v = *(const uint2*)&g_h1h[(size_t)s * 128 + fo];
        float2 f;
        f = __half22float2(*(__half2*)&v.x); a0 += f.x * w; a1 += f.y * w;
        f = __half22float2(*(__half2*)&v.y); a2 += f.x * w; a3 += f.y * w;
    }
    float inv = 1.f / (den + 1e-16f);
    float4 bb = *(const float4*)&b1[fo * 2];   // 4 consecutive features
    float o0 = a0 * inv + bb.x, o1 = a1 * inv + bb.y;
    float o2 = a2 * inv + bb.z, o3 = a3 * inv + bb.w;
    o0 = o0 > 0.f ? o0 : __expf(o0) - 1.f; o1 = o1 > 0.f ? o1 : __expf(o1) - 1.f;
    o2 = o2 > 0.f ? o2 : __expf(o2) - 1.f; o3 = o3 > 0.f ? o3 : __expf(o3) - 1.f;
    __half2* op = &g_hh[(size_t)node * 128 + fo];
    op[0] = __floats2half2_rn(o0, o1);
    op[1] = __floats2half2_rn(o2, o3);
}

// ---- fused GAT layer-2 aggregation + L2 normalize (fp16 gather, x4) -------
__global__ void k_agg2(const float* __restrict__ b2, float* __restrict__ zout) {
    int node = (blockIdx.x * blockDim.x + threadIdx.x) >> 5;
    int lane = threadIdx.x & 31;
    if (node >= NN) return;
    int beg = g_off[node], end = g_off[node + 1];
    float ad = g_ad2[node];

    float acc0 = 0.f, acc1 = 0.f, den = 0.f;
    int i = beg;
    for (; i + 4 <= end; i += 4) {
        int s0 = g_srcid[i], s1 = g_srcid[i + 1], s2 = g_srcid[i + 2], s3 = g_srcid[i + 3];
        float e0 = g_as2[s0], e1 = g_as2[s1], e2 = g_as2[s2], e3 = g_as2[s3];
        float2 h0 = __half22float2(g_h2h[(size_t)s0 * 32 + lane]);
        float2 h1 = __half22float2(g_h2h[(size_t)s1 * 32 + lane]);
        float2 h2 = __half22float2(g_h2h[(size_t)s2 * 32 + lane]);
        float2 h3 = __half22float2(g_h2h[(size_t)s3 * 32 + lane]);
        float w0 = __expf(lrelu(e0 + ad));
        float w1 = __expf(lrelu(e1 + ad));
        float w2 = __expf(lrelu(e2 + ad));
        float w3 = __expf(lrelu(e3 + ad));
        den += (w0 + w1) + (w2 + w3);
        acc0 += h0.x * w0 + h1.x * w1 + h2.x * w2 + h3.x * w3;
        acc1 += h0.y * w0 + h1.y * w1 + h2.y * w2 + h3.y * w3;
    }
    for (; i < end; i++) {
        int s = g_srcid[i];
        float w = __expf(lrelu(g_as2[s] + ad));
        den += w;
        float2 h = __half22float2(g_h2h[(size_t)s * 32 + lane]);
        acc0 += h.x * w; acc1 += h.y * w;
    }
    float inv = 1.f / (den + 1e-16f);
    float2 bb = *(const float2*)&b2[lane * 2];
    float z0 = acc0 * inv + bb.x;
    float z1 = acc1 * inv + bb.y;
    float ss = z0 * z0 + z1 * z1;
    #pragma unroll
    for (int o = 16; o > 0; o >>= 1)
        ss += __shfl_xor_sync(0xffffffffu, ss, o);
    float invn = 1.f / fmaxf(sqrtf(ss), 1e-12f);
    float2* zp = (float2*)&zout[(size_t)node * 64 + lane * 2];
    *zp = make_float2(z0 * invn, z1 * invn);
}

// ---------------- launcher ---------------------------------------------------
extern "C" void kernel_launch(void* const* d_in, const int* in_sizes, int n_in,
                              void* d_out, int out_size) {
    float* z = (float*)d_out;                       // [NN,64]
    float* xhat = (out_size >= 9600000) ? (z + (size_t)NN * 64) : 0;

    if (out_size != 9600000)
        k_zero_out<<<(out_size + 511) / 512, 512>>>((float*)d_out, out_size);

    // device addresses of scratch globals (host-passable)
    void *p_xh, *p_w1h, *p_w2h, *p_h1h, *p_hh, *p_h2h, *p_t;
    void *p_as1, *p_ad1, *p_as2, *p_ad2;
    cudaGetSymbolAddress(&p_xh,  g_xh);
    cudaGetSymbolAddress(&p_w1h, g_w1h);
    cudaGetSymbolAddress(&p_w2h, g_w2h);
    cudaGetSymbolAddress(&p_h1h, g_h1h);
    cudaGetSymbolAddress(&p_hh,  g_hh);
    cudaGetSymbolAddress(&p_h2h, g_h2h);
    cudaGetSymbolAddress(&p_t,   g_t);
    cudaGetSymbolAddress(&p_as1, g_as1);
    cudaGetSymbolAddress(&p_ad1, g_ad1);
    cudaGetSymbolAddress(&p_as2, g_as2);
    cudaGetSymbolAddress(&p_ad2, g_ad2);

    // ---- input resolution: positional (dict order) verified by sizes ----
    static const int expect[14] = {6400000, 1600000, 32768, 256, 256, 256,
                                   16384, 64, 64, 64, 4096, 64, 8192, 128};
    bool positionalOK = (n_in == 14);
    if (positionalOK) {
        for (int i = 0; i < 14; i++) {
            int s = in_sizes[i];
            if (s != expect[i] && !(i == 1 && s == 3200000)) { positionalOK = false; break; }
        }
    }

    const float *x = 0, *W1 = 0, *W2 = 0, *dW1 = 0, *dW2 = 0, *db2 = 0;
    const float *atts1 = 0, *attd1 = 0, *b1 = 0, *atts2 = 0, *attd2 = 0, *b2 = 0, *db1 = 0;
    const int* ei = 0;

    if (positionalOK) {
        x     = (const float*)d_in[0];
        ei    = (const int*)  d_in[1];
        W1    = (const float*)d_in[2];
        atts1 = (const float*)d_in[3];
        attd1 = (const float*)d_in[4];
        b1    = (const float*)d_in[5];
        W2    = (const float*)d_in[6];
        atts2 = (const float*)d_in[7];
        attd2 = (const float*)d_in[8];
        b2    = (const float*)d_in[9];
        dW1   = (const float*)d_in[10];
        db1   = (const float*)d_in[11];
        dW2   = (const float*)d_in[12];
        db2   = (const float*)d_in[13];
    } else {
        const float* g256[3] = {0, 0, 0};
        const float* g64[4]  = {0, 0, 0, 0};
        int n256 = 0, n64 = 0;
        for (int i = 0; i < n_in; i++) {
            int s = in_sizes[i];
            const float* p = (const float*)d_in[i];
            if      (s == 6400000) x   = p;
            else if (s == 1600000 || s == 3200000) ei = (const int*)d_in[i];
            else if (s == 32768)   W1  = p;
            else if (s == 16384)   W2  = p;
            else if (s == 4096)    dW1 = p;
            else if (s == 8192)    dW2 = p;
            else if (s == 128)     db2 = p;
            else if (s == 256 && n256 < 3) g256[n256++] = p;
            else if (s == 64  && n64  < 4) g64[n64++]   = p;
        }
        bool dictLike = (n_in > 0 && in_sizes[0] == 6400000);
        atts1 = g256[dictLike ? 0 : 1];
        attd1 = g256[dictLike ? 1 : 0];
        b1    = g256[2];
        atts2 = g64[dictLike ? 0 : 1];
        attd2 = g64[dictLike ? 1 : 0];
        b2    = g64[2];
        db1   = g64[3];
        if (!x || !ei || !W1 || !W2 || !dW1 || !dW2 || !db2 || n256 < 3 || n64 < 4) {
            k_flag<<<1, 1>>>(z, 1e12f);
            return;
        }
    }

    // ---- init + CSR ----
    k_init <<<(NN + 255) / 256, 256>>>(ei);
    k_count<<<(ET + 255) / 256, 256>>>(ei);
    k_scan1<<<1, 1024>>>();
    k_scatter<<<(ET + 255) / 256, 256>>>(ei);

    // ---- fp16 conversion ----
    k_cvt<<<(XPAIRS + W1PAIRS + W2PAIRS + 255) / 256, 256>>>(x, W1, W2);

    // ---- layer 1: tensor-core GEMM + fused att1 ----
    {
        dim3 g(4, (NN + 127) / 128);
        k_hgemm_att<128, 4><<<g, 256>>>((const __half*)p_xh, (const __half*)p_w1h,
                                        (__half2*)p_h1h, NN, 256,
                                        atts1, attd1, (float*)p_as1, (float*)p_ad1);
    }
    k_agg1<<<(NN * 64 + 255) / 256, 256>>>(b1);   // 2 warps per node

    // ---- layer 2: tensor-core GEMM + fused att2 ----
    {
        dim3 g(1, (NN + 127) / 128);
        k_hgemm_att<256, 1><<<g, 256>>>((const __half*)p_hh, (const __half*)p_w2h,
                                        (__half2*)p_h2h, NN, 64,
                                        atts2, attd2, (float*)p_as2, (float*)p_ad2);
    }
    k_agg2<<<(NN * 32 + 255) / 256, 256>>>(b2, z);

    // ---- decoder as two fp32 GEMMs (measured faster than fused in R11) ----
    if (xhat) {
        dim3 g1(1, (NN + 127) / 128);
        k_gemm64<<<g1, 256>>>(z, dW1, (float*)p_t, NN, 64, 64, db1, 2);
        dim3 g2(2, (NN + 127) / 128);
        k_gemm64<<<g2, 256>>>((float*)p_t, dW2, xhat, NN, 64, 128, db2, 1);
    }
}

// round 13
// speedup vs baseline: 1.1853x; 1.1853x over previous
#include <cuda_runtime.h>
#include <cuda_fp16.h>
#include <cstdint>
#include <math.h>

#define NN 50000
#define EE 800000
#define ET (NN + EE)          // 850000 edges incl. self loops

// ---------------- scratch (device globals; no allocation allowed) ----------
__device__ __half  g_xh[(size_t)NN * 128];   // x in fp16
__device__ __half  g_w1h[128 * 256];         // W1 fp16
__device__ __half  g_w2h[256 * 64];          // W2 fp16
__device__ __half  g_dw1h[64 * 64];          // dW1 fp16
__device__ __half  g_dw2h[64 * 128];         // dW2 fp16
__device__ __half2 g_h1h[(size_t)NN * 128];  // h1 fp16 (gather + att src)
__device__ __half2 g_hh [(size_t)NN * 128];  // elu(gat1) fp16 (input to GEMM2)
__device__ __half2 g_h2h[(size_t)NN * 32];   // h2 fp16
__device__ __half2 g_zh [(size_t)NN * 32];   // z fp16 (decoder input)
__device__ __half2 g_th [(size_t)NN * 32];   // decoder hidden fp16
__device__ float g_as1[NN * 4];
__device__ float g_ad1[NN * 4];
__device__ float g_as2[NN];
__device__ float g_ad2[NN];
__device__ int   g_deg[NN];
__device__ int   g_off[NN + 1];
__device__ int   g_cur[NN];
__device__ int   g_srcid[ET];
__device__ int   g_ei64;

__device__ __forceinline__ float lrelu(float v) { return v >= 0.f ? v : 0.2f * v; }

__device__ __forceinline__ int load_edge(const int* __restrict__ ei, int j) {
    return g_ei64 ? ei[(size_t)j * 2] : ei[j];   // little-endian low word
}

__global__ void k_flag(float* __restrict__ z, float v) { z[0] = v; }

__global__ void k_zero_out(float* __restrict__ o, int n) {
    int i = blockIdx.x * blockDim.x + threadIdx.x;
    if (i < n) o[i] = 0.f;
}

// ------- init: zero degrees + att accumulators + dtype detect --------------
__global__ void k_init(const int* __restrict__ ei) {
    int i = blockIdx.x * blockDim.x + threadIdx.x;
    if (i < NN) {
        g_deg[i] = 0;
        g_as2[i] = 0.f; g_ad2[i] = 0.f;
        #pragma unroll
        for (int h = 0; h < 4; h++) { g_as1[i * 4 + h] = 0.f; g_ad1[i * 4 + h] = 0.f; }
    }
    if (i == 0) {
        int odd_nz = 0, even_nz = 0;
        for (int j = 0; j < 256; j += 2) {
            if (ei[j]     != 0) even_nz++;
            if (ei[j + 1] != 0) odd_nz++;
        }
        g_ei64 = (odd_nz == 0 && even_nz > 0) ? 1 : 0;
    }
}

// ------- fp32 -> fp16 conversion of x, W1, W2, dW1, dW2 (pairwise) ----------
#define XPAIRS 3200000
#define W1PAIRS 16384
#define W2PAIRS 8192
#define DW1PAIRS 2048
#define DW2PAIRS 4096
#define CVT_TOTAL (XPAIRS + W1PAIRS + W2PAIRS + DW1PAIRS + DW2PAIRS)
__global__ void k_cvt(const float* __restrict__ x, const float* __restrict__ W1,
                      const float* __restrict__ W2, const float* __restrict__ dW1,
                      const float* __restrict__ dW2) {
    int p = blockIdx.x * blockDim.x + threadIdx.x;
    if (p < XPAIRS) {
        float2 v = *(const float2*)&x[(size_t)p * 2];
        *(__half2*)&g_xh[(size_t)p * 2] = __floats2half2_rn(v.x, v.y);
    } else if (p < XPAIRS + W1PAIRS) {
        int q = p - XPAIRS;
        float2 v = *(const float2*)&W1[(size_t)q * 2];
        *(__half2*)&g_w1h[(size_t)q * 2] = __floats2half2_rn(v.x, v.y);
    } else if (p < XPAIRS + W1PAIRS + W2PAIRS) {
        int q = p - XPAIRS - W1PAIRS;
        float2 v = *(const float2*)&W2[(size_t)q * 2];
        *(__half2*)&g_w2h[(size_t)q * 2] = __floats2half2_rn(v.x, v.y);
    } else if (p < XPAIRS + W1PAIRS + W2PAIRS + DW1PAIRS) {
        int q = p - XPAIRS - W1PAIRS - W2PAIRS;
        float2 v = *(const float2*)&dW1[(size_t)q * 2];
        *(__half2*)&g_dw1h[(size_t)q * 2] = __floats2half2_rn(v.x, v.y);
    } else if (p < CVT_TOTAL) {
        int q = p - XPAIRS - W1PAIRS - W2PAIRS - DW1PAIRS;
        float2 v = *(const float2*)&dW2[(size_t)q * 2];
        *(__half2*)&g_dw2h[(size_t)q * 2] = __floats2half2_rn(v.x, v.y);
    }
}

// ---------------- CSR build -------------------------------------------------
__global__ void k_count(const int* __restrict__ ei) {
    int e = blockIdx.x * blockDim.x + threadIdx.x;
    if (e >= ET) return;
    int dst = (e < EE) ? load_edge(ei, EE + e) : (e - EE);
    if ((unsigned)dst < (unsigned)NN) atomicAdd(&g_deg[dst], 1);
}

__global__ void k_scan1() {
    const int PER = 49;
    __shared__ int ws[32];
    int tid = threadIdx.x;
    int base = tid * PER;
    int sum = 0;
    for (int j = 0; j < PER; j++) { int idx = base + j; if (idx < NN) sum += g_deg[idx]; }
    int lane = tid & 31, w = tid >> 5;
    int v = sum;
    #pragma unroll
    for (int o = 1; o < 32; o <<= 1) {
        int t = __shfl_up_sync(0xffffffffu, v, o);
        if (lane >= o) v += t;
    }
    if (lane == 31) ws[w] = v;
    __syncthreads();
    if (w == 0) {
        int xv = ws[lane];
        #pragma unroll
        for (int o = 1; o < 32; o <<= 1) {
            int t = __shfl_up_sync(0xffffffffu, xv, o);
            if (lane >= o) xv += t;
        }
        ws[lane] = xv;
    }
    __syncthreads();
    int run = (v - sum) + (w > 0 ? ws[w - 1] : 0);
    for (int j = 0; j < PER; j++) {
        int idx = base + j;
        if (idx < NN) {
            int d = g_deg[idx];
            g_off[idx] = run; g_cur[idx] = run;
            run += d;
        }
    }
    if (tid == 0) g_off[NN] = ET;
}

__global__ void k_scatter(const int* __restrict__ ei) {
    int e = blockIdx.x * blockDim.x + threadIdx.x;
    if (e >= ET) return;
    int s, d;
    if (e < EE) { s = load_edge(ei, e); d = load_edge(ei, EE + e); }
    else        { s = d = e - EE; }
    if ((unsigned)d >= (unsigned)NN || (unsigned)s >= (unsigned)NN) return;
    int p = atomicAdd(&g_cur[d], 1);
    if ((unsigned)p < (unsigned)ET) g_srcid[p] = s;
}

// ------- fp16 tensor-core GEMM + fused attention-coefficient epilogue ------
template<int K, int HS>
__global__ void k_hgemm_att(const __half* __restrict__ A, const __half* __restrict__ B,
                            __half2* __restrict__ Ch, int M, int N,
                            const float* __restrict__ att_s, const float* __restrict__ att_d,
                            float* __restrict__ as_out, float* __restrict__ ad_out) {
    __shared__ __half As[128][40];
    __shared__ __half Bs[64][42];
    int bm = blockIdx.y * 128, bn = blockIdx.x * 64;
    int tid = threadIdx.x, lane = tid & 31, wid = tid >> 5;
    int wm = wid & 3, wn = wid >> 2;
    int g = lane >> 2, tc = lane & 3;
    float acc[2][4][4] = {};
    for (int k0 = 0; k0 < K; k0 += 32) {
        #pragma unroll
        for (int t = 0; t < 2; t++) {
            int i = tid + t * 256;
            int r = i >> 2, seg = i & 3;
            int row = bm + r;
            uint4 v = make_uint4(0u, 0u, 0u, 0u);
            if (row < M) v = *(const uint4*)&A[(size_t)row * K + k0 + seg * 8];
            *(uint4*)&As[r][seg * 8] = v;
        }
        #pragma unroll
        for (int t = 0; t < 4; t++) {
            int i = tid + t * 256;
            int kk = i >> 5, nn = (i & 31) * 2;
            __half2 v = *(const __half2*)&B[(size_t)(k0 + kk) * N + bn + nn];
            Bs[nn][kk]     = __low2half(v);
            Bs[nn + 1][kk] = __high2half(v);
        }
        __syncthreads();
        #pragma unroll
        for (int ks = 0; ks < 2; ks++) {
            int kb = ks * 16;
            uint32_t af[2][4], bf[4][2];
            #pragma unroll
            for (int mt = 0; mt < 2; mt++) {
                int r = wm * 32 + mt * 16 + g;
                af[mt][0] = *(const uint32_t*)&As[r][kb + tc * 2];
                af[mt][1] = *(const uint32_t*)&As[r + 8][kb + tc * 2];
                af[mt][2] = *(const uint32_t*)&As[r][kb + tc * 2 + 8];
                af[mt][3] = *(const uint32_t*)&As[r + 8][kb + tc * 2 + 8];
            }
            #pragma unroll
            for (int nt = 0; nt < 4; nt++) {
                int n = wn * 32 + nt * 8 + g;
                bf[nt][0] = *(const uint32_t*)&Bs[n][kb + tc * 2];
                bf[nt][1] = *(const uint32_t*)&Bs[n][kb + tc * 2 + 8];
            }
            #pragma unroll
            for (int mt = 0; mt < 2; mt++)
                #pragma unroll
                for (int nt = 0; nt < 4; nt++)
                    asm volatile(
                        "mma.sync.aligned.m16n8k16.row.col.f32.f16.f16.f32 "
                        "{%0,%1,%2,%3},{%4,%5,%6,%7},{%8,%9},{%0,%1,%2,%3};"
                        : "+f"(acc[mt][nt][0]), "+f"(acc[mt][nt][1]),
                          "+f"(acc[mt][nt][2]), "+f"(acc[mt][nt][3])
                        : "r"(af[mt][0]), "r"(af[mt][1]), "r"(af[mt][2]), "r"(af[mt][3]),
                          "r"(bf[nt][0]), "r"(bf[nt][1]));
        }
        __syncthreads();
    }
    int hh = bn >> 6;
    int N2 = N >> 1;
    #pragma unroll
    for (int mt = 0; mt < 2; mt++) {
        #pragma unroll
        for (int hf = 0; hf < 2; hf++) {
            int row = bm + wm * 32 + mt * 16 + g + hf * 8;
            float ps = 0.f, pd = 0.f;
            if (row < M) {
                #pragma unroll
                for (int nt = 0; nt < 4; nt++) {
                    int cl = wn * 32 + nt * 8 + tc * 2;
                    float v0 = acc[mt][nt][hf * 2 + 0];
                    float v1 = acc[mt][nt][hf * 2 + 1];
                    Ch[(size_t)row * N2 + ((bn + cl) >> 1)] = __floats2half2_rn(v0, v1);
                    ps += v0 * att_s[bn + cl] + v1 * att_s[bn + cl + 1];
                    pd += v0 * att_d[bn + cl] + v1 * att_d[bn + cl + 1];
                }
            }
            ps += __shfl_xor_sync(0xffffffffu, ps, 1);
            pd += __shfl_xor_sync(0xffffffffu, pd, 1);
            ps += __shfl_xor_sync(0xffffffffu, ps, 2);
            pd += __shfl_xor_sync(0xffffffffu, pd, 2);
            if (tc == 0 && row < M) {
                atomicAdd(&as_out[row * HS + hh], ps);
                atomicAdd(&ad_out[row * HS + hh], pd);
            }
        }
    }
}

// ------- fp16 tensor-core GEMM, bias(+ELU) epilogue, fp16 or fp32 out ------
// BM=128, BN=64, BK=32, 256 threads. For decoder stages (K=64).
template<int K, bool ELU, bool HALF_OUT>
__global__ void k_hgemm_epi(const __half* __restrict__ A, const __half* __restrict__ B,
                            __half2* __restrict__ Ch, float* __restrict__ Cf,
                            int M, int N, const float* __restrict__ bias) {
    __shared__ __half As[128][40];
    __shared__ __half Bs[64][42];
    int bm = blockIdx.y * 128, bn = blockIdx.x * 64;
    int tid = threadIdx.x, lane = tid & 31, wid = tid >> 5;
    int wm = wid & 3, wn = wid >> 2;
    int g = lane >> 2, tc = lane & 3;
    float acc[2][4][4] = {};
    for (int k0 = 0; k0 < K; k0 += 32) {
        #pragma unroll
        for (int t = 0; t < 2; t++) {
            int i = tid + t * 256;
            int r = i >> 2, seg = i & 3;
            int row = bm + r;
            uint4 v = make_uint4(0u, 0u, 0u, 0u);
            if (row < M) v = *(const uint4*)&A[(size_t)row * K + k0 + seg * 8];
            *(uint4*)&As[r][seg * 8] = v;
        }
        #pragma unroll
        for (int t = 0; t < 4; t++) {
            int i = tid + t * 256;
            int kk = i >> 5, nn = (i & 31) * 2;
            __half2 v = *(const __half2*)&B[(size_t)(k0 + kk) * N + bn + nn];
            Bs[nn][kk]     = __low2half(v);
            Bs[nn + 1][kk] = __high2half(v);
        }
        __syncthreads();
        #pragma unroll
        for (int ks = 0; ks < 2; ks++) {
            int kb = ks * 16;
            uint32_t af[2][4], bf[4][2];
            #pragma unroll
            for (int mt = 0; mt < 2; mt++) {
                int r = wm * 32 + mt * 16 + g;
                af[mt][0] = *(const uint32_t*)&As[r][kb + tc * 2];
                af[mt][1] = *(const uint32_t*)&As[r + 8][kb + tc * 2];
                af[mt][2] = *(const uint32_t*)&As[r][kb + tc * 2 + 8];
                af[mt][3] = *(const uint32_t*)&As[r + 8][kb + tc * 2 + 8];
            }
            #pragma unroll
            for (int nt = 0; nt < 4; nt++) {
                int n = wn * 32 + nt * 8 + g;
                bf[nt][0] = *(const uint32_t*)&Bs[n][kb + tc * 2];
                bf[nt][1] = *(const uint32_t*)&Bs[n][kb + tc * 2 + 8];
            }
            #pragma unroll
            for (int mt = 0; mt < 2; mt++)
                #pragma unroll
                for (int nt = 0; nt < 4; nt++)
                    asm volatile(
                        "mma.sync.aligned.m16n8k16.row.col.f32.f16.f16.f32 "
                        "{%0,%1,%2,%3},{%4,%5,%6,%7},{%8,%9},{%0,%1,%2,%3};"
                        : "+f"(acc[mt][nt][0]), "+f"(acc[mt][nt][1]),
                          "+f"(acc[mt][nt][2]), "+f"(acc[mt][nt][3])
                        : "r"(af[mt][0]), "r"(af[mt][1]), "r"(af[mt][2]), "r"(af[mt][3]),
                          "r"(bf[nt][0]), "r"(bf[nt][1]));
        }
        __syncthreads();
    }
    int N2 = N >> 1;
    #pragma unroll
    for (int mt = 0; mt < 2; mt++) {
        #pragma unroll
        for (int hf = 0; hf < 2; hf++) {
            int row = bm + wm * 32 + mt * 16 + g + hf * 8;
            if (row >= M) continue;
            #pragma unroll
            for (int nt = 0; nt < 4; nt++) {
                int cl = bn + wn * 32 + nt * 8 + tc * 2;
                float v0 = acc[mt][nt][hf * 2 + 0] + bias[cl];
                float v1 = acc[mt][nt][hf * 2 + 1] + bias[cl + 1];
                if (ELU) {
                    v0 = v0 > 0.f ? v0 : __expf(v0) - 1.f;
                    v1 = v1 > 0.f ? v1 : __expf(v1) - 1.f;
                }
                if (HALF_OUT)
                    Ch[(size_t)row * N2 + (cl >> 1)] = __floats2half2_rn(v0, v1);
                else
                    *(float2*)&Cf[(size_t)row * N + cl] = make_float2(v0, v1);
            }
        }
    }
}

// ---- fused GAT layer-1 aggregation (warp/node, fp16 gather, unroll x2) ----
__global__ void k_agg1(const float* __restrict__ b1) {
    int node = (blockIdx.x * blockDim.x + threadIdx.x) >> 5;
    int lane = threadIdx.x & 31;
    if (node >= NN) return;
    int beg = g_off[node], end = g_off[node + 1];
    int hh = lane >> 3;
    float adh = g_ad1[node * 4 + hh];

    float a0=0,a1=0,a2=0,a3=0,a4=0,a5=0,a6=0,a7=0;
    float den = 0.f;
    int i = beg;
    for (; i + 2 <= end; i += 2) {
        int s0 = g_srcid[i], s1 = g_srcid[i + 1];
        float as0 = g_as1[s0 * 4 + hh], as1v = g_as1[s1 * 4 + hh];
        uint4 v0 = *(const uint4*)&g_h1h[(size_t)s0 * 128 + lane * 4];
        uint4 v1 = *(const uint4*)&g_h1h[(size_t)s1 * 128 + lane * 4];
        float w0 = __expf(lrelu(as0 + adh));
        float w1 = __expf(lrelu(as1v + adh));
        den += w0 + w1;
        float2 f;
        f = __half22float2(*(__half2*)&v0.x); a0 += f.x * w0; a1 += f.y * w0;
        f = __half22float2(*(__half2*)&v0.y); a2 += f.x * w0; a3 += f.y * w0;
        f = __half22float2(*(__half2*)&v0.z); a4 += f.x * w0; a5 += f.y * w0;
        f = __half22float2(*(__half2*)&v0.w); a6 += f.x * w0; a7 += f.y * w0;
        f = __half22float2(*(__half2*)&v1.x); a0 += f.x * w1; a1 += f.y * w1;
        f = __half22float2(*(__half2*)&v1.y); a2 += f.x * w1; a3 += f.y * w1;
        f = __half22float2(*(__half2*)&v1.z); a4 += f.x * w1; a5 += f.y * w1;
        f = __half22float2(*(__half2*)&v1.w); a6 += f.x * w1; a7 += f.y * w1;
    }
    if (i < end) {
        int s = g_srcid[i];
        float w = __expf(lrelu(g_as1[s * 4 + hh] + adh));
        den += w;
        uint4 v = *(const uint4*)&g_h1h[(size_t)s * 128 + lane * 4];
        float2 f;
        f = __half22float2(*(__half2*)&v.x); a0 += f.x * w; a1 += f.y * w;
        f = __half22float2(*(__half2*)&v.y); a2 += f.x * w; a3 += f.y * w;
        f = __half22float2(*(__half2*)&v.z); a4 += f.x * w; a5 += f.y * w;
        f = __half22float2(*(__half2*)&v.w); a6 += f.x * w; a7 += f.y * w;
    }
    float inv = 1.f / (den + 1e-16f);
    const float4* bp = (const float4*)&b1[lane * 8];
    float4 bb0 = bp[0], bb1 = bp[1];
    float o0 = a0*inv+bb0.x, o1 = a1*inv+bb0.y, o2 = a2*inv+bb0.z, o3 = a3*inv+bb0.w;
    float o4 = a4*inv+bb1.x, o5 = a5*inv+bb1.y, o6 = a6*inv+bb1.z, o7 = a7*inv+bb1.w;
    o0 = o0 > 0.f ? o0 : __expf(o0) - 1.f; o1 = o1 > 0.f ? o1 : __expf(o1) - 1.f;
    o2 = o2 > 0.f ? o2 : __expf(o2) - 1.f; o3 = o3 > 0.f ? o3 : __expf(o3) - 1.f;
    o4 = o4 > 0.f ? o4 : __expf(o4) - 1.f; o5 = o5 > 0.f ? o5 : __expf(o5) - 1.f;
    o6 = o6 > 0.f ? o6 : __expf(o6) - 1.f; o7 = o7 > 0.f ? o7 : __expf(o7) - 1.f;
    __half2* op = &g_hh[(size_t)node * 128 + lane * 4];
    op[0] = __floats2half2_rn(o0, o1);
    op[1] = __floats2half2_rn(o2, o3);
    op[2] = __floats2half2_rn(o4, o5);
    op[3] = __floats2half2_rn(o6, o7);
}

// ---- fused GAT layer-2 agg + L2 normalize; writes fp32 z AND fp16 z -------
__global__ void k_agg2(const float* __restrict__ b2, float* __restrict__ zout) {
    int node = (blockIdx.x * blockDim.x + threadIdx.x) >> 5;
    int lane = threadIdx.x & 31;
    if (node >= NN) return;
    int beg = g_off[node], end = g_off[node + 1];
    float ad = g_ad2[node];

    float acc0 = 0.f, acc1 = 0.f, den = 0.f;
    int i = beg;
    for (; i + 2 <= end; i += 2) {
        int s0 = g_srcid[i], s1 = g_srcid[i + 1];
        float as0 = g_as2[s0], as1v = g_as2[s1];
        float2 h0 = __half22float2(g_h2h[(size_t)s0 * 32 + lane]);
        float2 h1 = __half22float2(g_h2h[(size_t)s1 * 32 + lane]);
        float w0 = __expf(lrelu(as0 + ad));
        float w1 = __expf(lrelu(as1v + ad));
        den += w0 + w1;
        acc0 += h0.x * w0 + h1.x * w1;
        acc1 += h0.y * w0 + h1.y * w1;
    }
    if (i < end) {
        int s = g_srcid[i];
        float w = __expf(lrelu(g_as2[s] + ad));
        den += w;
        float2 h = __half22float2(g_h2h[(size_t)s * 32 + lane]);
        acc0 += h.x * w; acc1 += h.y * w;
    }
    float inv = 1.f / (den + 1e-16f);
    float2 bb = *(const float2*)&b2[lane * 2];
    float z0 = acc0 * inv + bb.x;
    float z1 = acc1 * inv + bb.y;
    float ss = z0 * z0 + z1 * z1;
    #pragma unroll
    for (int o = 16; o > 0; o >>= 1)
        ss += __shfl_xor_sync(0xffffffffu, ss, o);
    float invn = 1.f / fmaxf(sqrtf(ss), 1e-12f);
    z0 *= invn; z1 *= invn;
    *(float2*)&zout[(size_t)node * 64 + lane * 2] = make_float2(z0, z1);
    g_zh[(size_t)node * 32 + lane] = __floats2half2_rn(z0, z1);
}

// ---------------- launcher ---------------------------------------------------
extern "C" void kernel_launch(void* const* d_in, const int* in_sizes, int n_in,
                              void* d_out, int out_size) {
    float* z = (float*)d_out;                       // [NN,64]
    float* xhat = (out_size >= 9600000) ? (z + (size_t)NN * 64) : 0;

    if (out_size != 9600000)
        k_zero_out<<<(out_size + 511) / 512, 512>>>((float*)d_out, out_size);

    // device addresses of scratch globals (host-passable)
    void *p_xh, *p_w1h, *p_w2h, *p_dw1h, *p_dw2h, *p_h1h, *p_hh, *p_h2h, *p_zh, *p_th;
    void *p_as1, *p_ad1, *p_as2, *p_ad2;
    cudaGetSymbolAddress(&p_xh,   g_xh);
    cudaGetSymbolAddress(&p_w1h,  g_w1h);
    cudaGetSymbolAddress(&p_w2h,  g_w2h);
    cudaGetSymbolAddress(&p_dw1h, g_dw1h);
    cudaGetSymbolAddress(&p_dw2h, g_dw2h);
    cudaGetSymbolAddress(&p_h1h,  g_h1h);
    cudaGetSymbolAddress(&p_hh,   g_hh);
    cudaGetSymbolAddress(&p_h2h,  g_h2h);
    cudaGetSymbolAddress(&p_zh,   g_zh);
    cudaGetSymbolAddress(&p_th,   g_th);
    cudaGetSymbolAddress(&p_as1,  g_as1);
    cudaGetSymbolAddress(&p_ad1,  g_ad1);
    cudaGetSymbolAddress(&p_as2,  g_as2);
    cudaGetSymbolAddress(&p_ad2,  g_ad2);

    // ---- input resolution: positional (dict order) verified by sizes ----
    static const int expect[14] = {6400000, 1600000, 32768, 256, 256, 256,
                                   16384, 64, 64, 64, 4096, 64, 8192, 128};
    bool positionalOK = (n_in == 14);
    if (positionalOK) {
        for (int i = 0; i < 14; i++) {
            int s = in_sizes[i];
            if (s != expect[i] && !(i == 1 && s == 3200000)) { positionalOK = false; break; }
        }
    }

    const float *x = 0, *W1 = 0, *W2 = 0, *dW1 = 0, *dW2 = 0, *db2 = 0;
    const float *atts1 = 0, *attd1 = 0, *b1 = 0, *atts2 = 0, *attd2 = 0, *b2 = 0, *db1 = 0;
    const int* ei = 0;

    if (positionalOK) {
        x     = (const float*)d_in[0];
        ei    = (const int*)  d_in[1];
        W1    = (const float*)d_in[2];
        atts1 = (const float*)d_in[3];
        attd1 = (const float*)d_in[4];
        b1    = (const float*)d_in[5];
        W2    = (const float*)d_in[6];
        atts2 = (const float*)d_in[7];
        attd2 = (const float*)d_in[8];
        b2    = (const float*)d_in[9];
        dW1   = (const float*)d_in[10];
        db1   = (const float*)d_in[11];
        dW2   = (const float*)d_in[12];
        db2   = (const float*)d_in[13];
    } else {
        const float* g256[3] = {0, 0, 0};
        const float* g64[4]  = {0, 0, 0, 0};
        int n256 = 0, n64 = 0;
        for (int i = 0; i < n_in; i++) {
            int s = in_sizes[i];
            const float* p = (const float*)d_in[i];
            if      (s == 6400000) x   = p;
            else if (s == 1600000 || s == 3200000) ei = (const int*)d_in[i];
            else if (s == 32768)   W1  = p;
            else if (s == 16384)   W2  = p;
            else if (s == 4096)    dW1 = p;
            else if (s == 8192)    dW2 = p;
            else if (s == 128)     db2 = p;
            else if (s == 256 && n256 < 3) g256[n256++] = p;
            else if (s == 64  && n64  < 4) g64[n64++]   = p;
        }
        bool dictLike = (n_in > 0 && in_sizes[0] == 6400000);
        atts1 = g256[dictLike ? 0 : 1];
        attd1 = g256[dictLike ? 1 : 0];
        b1    = g256[2];
        atts2 = g64[dictLike ? 0 : 1];
        attd2 = g64[dictLike ? 1 : 0];
        b2    = g64[2];
        db1   = g64[3];
        if (!x || !ei || !W1 || !W2 || !dW1 || !dW2 || !db2 || n256 < 3 || n64 < 4) {
            k_flag<<<1, 1>>>(z, 1e12f);
            return;
        }
    }

    // ---- init + CSR ----
    k_init <<<(NN + 255) / 256, 256>>>(ei);
    k_count<<<(ET + 255) / 256, 256>>>(ei);
    k_scan1<<<1, 1024>>>();
    k_scatter<<<(ET + 255) / 256, 256>>>(ei);

    // ---- fp16 conversion ----
    k_cvt<<<(CVT_TOTAL + 255) / 256, 256>>>(x, W1, W2, dW1, dW2);

    // ---- layer 1: tensor-core GEMM + fused att1 ----
    {
        dim3 g(4, (NN + 127) / 128);
        k_hgemm_att<128, 4><<<g, 256>>>((const __half*)p_xh, (const __half*)p_w1h,
                                        (__half2*)p_h1h, NN, 256,
                                        atts1, attd1, (float*)p_as1, (float*)p_ad1);
    }
    k_agg1<<<(NN * 32 + 255) / 256, 256>>>(b1);

    // ---- layer 2: tensor-core GEMM + fused att2 ----
    {
        dim3 g(1, (NN + 127) / 128);
        k_hgemm_att<256, 1><<<g, 256>>>((const __half*)p_hh, (const __half*)p_w2h,
                                        (__half2*)p_h2h, NN, 64,
                                        atts2, attd2, (float*)p_as2, (float*)p_ad2);
    }
    k_agg2<<<(NN * 32 + 255) / 256, 256>>>(b2, z);

    // ---- decoder: two fp16 tensor-core GEMMs ----
    if (xhat) {
        dim3 g1(1, (NN + 127) / 128);
        k_hgemm_epi<64, true, true><<<g1, 256>>>(
            (const __half*)p_zh, (const __half*)p_dw1h,
            (__half2*)p_th, (float*)0, NN, 64, db1);
        dim3 g2(2, (NN + 127) / 128);
        k_hgemm_epi<64, false, false><<<g2, 256>>>(
            (const __half*)p_th, (const __half*)p_dw2h,
            (__half2*)0, xhat, NN, 128, db2);
    }
}